// round 15
// baseline (speedup 1.0000x reference)
#include <cuda_runtime.h>
#include <cuda_fp16.h>
#include <math.h>
#include <stdint.h>

// ---------------- problem constants ----------------
#define BB   64
#define NT   196
#define DD   768
#define HH   8
#define HD   96
#define RR   (BB*NT)          // 12544 rows
#define D3   (3*DD)           // 2304
#define D4   (4*DD)           // 3072
#define ATTN_SCALE 0.10206207261596577f   // 96^-0.5
#define LN_EPS 1e-5f

// ---------------- scratch (device globals; no allocations allowed) ----------------
static __device__ float  g_hdw [BB*3*NT];
static __device__ __half g_xl_h [RR*DD];
static __device__ __half g_qkv_h[(size_t)RR*D3];
static __device__ __half g_att_h[RR*DD];
static __device__ float  g_x2  [RR*DD];
static __device__ __half g_h2_h[RR*DD];
static __device__ __half g_fc1_h[(size_t)RR*D4];
static __device__ float  g_maxn[RR];
static __device__ float  g_aven[RR];
static __device__ float  g_s1  [RR];
static __device__ float  g_gate[RR];
static __device__ float  g_aveg[BB];
// fp16 weight copies
static __device__ __half g_wqkv_h [(size_t)D3*DD];
static __device__ __half g_wproj_h[(size_t)DD*DD];
static __device__ __half g_wfc1_h [(size_t)D4*DD];
static __device__ __half g_wfc2_h [(size_t)DD*D4];

// ---------------- small helpers ----------------
__device__ __forceinline__ uint32_t smem_u32(const void* p){
    uint32_t a;
    asm("{ .reg .u64 t; cvta.to.shared.u64 t, %1; cvt.u32.u64 %0, t; }" : "=r"(a) : "l"(p));
    return a;
}
__device__ __forceinline__ void cp16(uint32_t dst, const void* src){
    asm volatile("cp.async.cg.shared.global [%0], [%1], 16;" :: "r"(dst), "l"(src));
}
__device__ __forceinline__ void cp_commit(){ asm volatile("cp.async.commit_group;" ::: "memory"); }
template<int N> __device__ __forceinline__ void cp_wait(){
    asm volatile("cp.async.wait_group %0;" :: "n"(N) : "memory");
}
__device__ __forceinline__ void mma_f16(float c[4],
        uint32_t a0, uint32_t a1, uint32_t a2, uint32_t a3,
        uint32_t b0, uint32_t b1){
    asm volatile("mma.sync.aligned.m16n8k16.row.col.f32.f16.f16.f32 "
        "{%0,%1,%2,%3}, {%4,%5,%6,%7}, {%8,%9}, {%0,%1,%2,%3};"
        : "+f"(c[0]), "+f"(c[1]), "+f"(c[2]), "+f"(c[3])
        : "r"(a0), "r"(a1), "r"(a2), "r"(a3), "r"(b0), "r"(b1));
}
__device__ __forceinline__ void ldsm_x4(uint32_t addr,
        uint32_t& r0, uint32_t& r1, uint32_t& r2, uint32_t& r3){
    asm volatile("ldmatrix.sync.aligned.m8n8.x4.shared.b16 {%0,%1,%2,%3}, [%4];"
        : "=r"(r0), "=r"(r1), "=r"(r2), "=r"(r3) : "r"(addr));
}
__device__ __forceinline__ void ldsm_x4_t(uint32_t addr,
        uint32_t& r0, uint32_t& r1, uint32_t& r2, uint32_t& r3){
    asm volatile("ldmatrix.sync.aligned.m8n8.x4.trans.shared.b16 {%0,%1,%2,%3}, [%4];"
        : "=r"(r0), "=r"(r1), "=r"(r2), "=r"(r3) : "r"(addr));
}
__device__ __forceinline__ void h8_to_f8(uint4 t, float* dst){
    float2 f0 = __half22float2(*(__half2*)&t.x);
    float2 f1 = __half22float2(*(__half2*)&t.y);
    float2 f2 = __half22float2(*(__half2*)&t.z);
    float2 f3 = __half22float2(*(__half2*)&t.w);
    dst[0]=f0.x; dst[1]=f0.y; dst[2]=f1.x; dst[3]=f1.y;
    dst[4]=f2.x; dst[5]=f2.y; dst[6]=f3.x; dst[7]=f3.y;
}

// ---------------- all-weights fp16 conversion (single launch) ----------------
#define N4_QKV  (D3*DD/4)
#define N4_PROJ (DD*DD/4)
#define N4_FC1  (D4*DD/4)
#define N4_FC2  (DD*D4/4)
#define N4_ALL  (N4_QKV + N4_PROJ + N4_FC1 + N4_FC2)
__global__ void f2h_all_kernel(const float4* __restrict__ qkv_w,
                               const float4* __restrict__ proj_w,
                               const float4* __restrict__ fc1_w,
                               const float4* __restrict__ fc2_w){
    int i = blockIdx.x*blockDim.x + threadIdx.x;
    if (i >= N4_ALL) return;
    const float4* s; uint2* d; int j = i;
    if (j < N4_QKV){ s = qkv_w; d = (uint2*)g_wqkv_h; }
    else if ((j -= N4_QKV) < N4_PROJ){ s = proj_w; d = (uint2*)g_wproj_h; }
    else if ((j -= N4_PROJ) < N4_FC1){ s = fc1_w; d = (uint2*)g_wfc1_h; }
    else { j -= N4_FC1; s = fc2_w; d = (uint2*)g_wfc2_h; }
    float4 v = s[j];
    uint2 o;
    *(__half2*)&o.x = __floats2half2_rn(v.x, v.y);
    *(__half2*)&o.y = __floats2half2_rn(v.z, v.w);
    d[j] = o;
}

// ============================================================================
// fp16 mma.sync GEMM, cp.async 5-stage (K-tile 32), ldmatrix fragments.
// C[M,N] = A[M,K] @ W[N,K]^T
// EPI: 1 bias+GELU -> half ; 2 bias + res(fp32) -> fp32 ;
//      3 plain -> half     ; 4 bias + (res fp32 + res2[row%NT] fp32) -> fp32
// ============================================================================
#define NSTG 5
#define TSH  40
#define TILEB (128*TSH*2)
#define STGB  (2*TILEB)
#define MMA_SMEM (NSTG*STGB)               // 102400 B -> 2 CTAs/SM

template<int EPI>
__global__ __launch_bounds__(256,2) void hgemm(int M, int N, int K,
        const __half* __restrict__ A, const __half* __restrict__ W,
        const float* __restrict__ bias, const float* __restrict__ res,
        const float* __restrict__ res2, void* __restrict__ Cout){
    extern __shared__ char smc[];
    uint32_t sbase = smem_u32(smc);
    int tid = threadIdx.x, wid = tid >> 5, lane = tid & 31;
    int bm = blockIdx.y, bn = blockIdx.x;
    const __half* Ab = A + (size_t)bm*128*K;
    const __half* Wb = W + (size_t)bn*128*K;
    int nk = K >> 5;

    int wm = (wid & 1) * 64;
    int wn = (wid >> 1) * 32;
    int g  = lane >> 2, tg = lane & 3;

    uint32_t aAddr[4];
    #pragma unroll
    for (int mi=0;mi<4;mi++)
        aAddr[mi] = (uint32_t)(((wm + 16*mi + (lane & 15))*TSH + 8*(lane >> 4)) * 2);
    uint32_t bAddr[2];
    #pragma unroll
    for (int ko=0;ko<2;ko++)
        bAddr[ko] = (uint32_t)(TILEB + ((wn + lane)*TSH + 8*ko) * 2);

    int srow = tid & 127;
    const __half* gsrc = ((tid < 128) ? Ab : Wb) + (size_t)srow*K;
    uint32_t sdst = ((tid < 128) ? 0u : (uint32_t)TILEB) + (uint32_t)srow*(TSH*2);

    #pragma unroll
    for (int s=0; s<NSTG-1; s++){
        uint32_t base = sbase + s*STGB + sdst;
        const __half* gp = gsrc + (s << 5);
        #pragma unroll
        for (int kc=0; kc<4; kc++) cp16(base + kc*16, gp + kc*8);
        cp_commit();
    }

    float c[4][4][4];
    #pragma unroll
    for (int mi=0;mi<4;mi++)
        #pragma unroll
        for (int nj=0;nj<4;nj++)
            #pragma unroll
            for (int e=0;e<4;e++) c[mi][nj][e] = 0.f;

    for (int kt=0; kt<nk; kt++){
        cp_wait<NSTG-2>();
        __syncthreads();
        if (kt + NSTG-1 < nk){
            int s = (kt + NSTG-1) % NSTG;
            uint32_t base = sbase + s*STGB + sdst;
            const __half* gp = gsrc + ((kt + NSTG-1) << 5);
            #pragma unroll
            for (int kc=0; kc<4; kc++) cp16(base + kc*16, gp + kc*8);
        }
        cp_commit();

        uint32_t stg = sbase + (uint32_t)((kt % NSTG) * STGB);
        #pragma unroll
        for (int ks=0; ks<2; ks++){
            uint32_t kboff = (uint32_t)(ks*16*2);
            uint32_t a[4][4], b[4][2];
            #pragma unroll
            for (int mi=0;mi<4;mi++)
                ldsm_x4(stg + aAddr[mi] + kboff, a[mi][0], a[mi][1], a[mi][2], a[mi][3]);
            #pragma unroll
            for (int ko=0;ko<2;ko++){
                uint32_t t0,t1,t2,t3;
                ldsm_x4(stg + bAddr[ko] + kboff, t0, t1, t2, t3);
                b[0][ko]=t0; b[1][ko]=t1; b[2][ko]=t2; b[3][ko]=t3;
            }
            #pragma unroll
            for (int mi=0;mi<4;mi++)
                #pragma unroll
                for (int nj=0;nj<4;nj++)
                    mma_f16(c[mi][nj], a[mi][0],a[mi][1],a[mi][2],a[mi][3], b[nj][0],b[nj][1]);
        }
    }

    #pragma unroll
    for (int mi=0;mi<4;mi++){
        int r0 = bm*128 + wm + 16*mi + g;
        #pragma unroll
        for (int rr=0; rr<2; rr++){
            int row = r0 + rr*8;
            #pragma unroll
            for (int nj=0;nj<4;nj++){
                int col = bn*128 + wn + 8*nj + tg*2;
                float v0 = c[mi][nj][rr*2+0];
                float v1 = c[mi][nj][rr*2+1];
                if (EPI != 3){ v0 += __ldg(bias+col); v1 += __ldg(bias+col+1); }
                if (EPI == 1){
                    v0 = 0.5f*v0*(1.0f + erff(v0*0.70710678118654752f));
                    v1 = 0.5f*v1*(1.0f + erff(v1*0.70710678118654752f));
                    __half* Crow = (__half*)Cout + (size_t)row*N;
                    *(__half2*)(Crow + col) = __floats2half2_rn(v0, v1);
                } else if (EPI == 2){
                    float2 r2 = *(const float2*)(res + (size_t)row*N + col);
                    v0 += r2.x; v1 += r2.y;
                    float* Crow = (float*)Cout + (size_t)row*N;
                    *(float2*)(Crow + col) = make_float2(v0, v1);
                } else if (EPI == 4){
                    float2 r2 = *(const float2*)(res + (size_t)row*N + col);
                    float2 p2 = *(const float2*)(res2 + (size_t)(row % NT)*N + col);
                    v0 += r2.x + p2.x; v1 += r2.y + p2.y;
                    float* Crow = (float*)Cout + (size_t)row*N;
                    *(float2*)(Crow + col) = make_float2(v0, v1);
                } else {
                    __half* Crow = (__half*)Cout + (size_t)row*N;
                    *(__half2*)(Crow + col) = __floats2half2_rn(v0, v1);
                }
            }
        }
    }
}

// ---------------- reductions ----------------
__device__ __forceinline__ float warpSum(float v){
    #pragma unroll
    for (int o=16;o;o>>=1) v += __shfl_xor_sync(0xffffffffu, v, o);
    return v;
}
__device__ __forceinline__ float warpMax(float v){
    #pragma unroll
    for (int o=16;o;o>>=1) v = fmaxf(v, __shfl_xor_sync(0xffffffffu, v, o));
    return v;
}
__device__ float blockSum(float v){
    __shared__ float sh[32];
    int lane = threadIdx.x & 31, w = threadIdx.x >> 5;
    v = warpSum(v);
    if (lane==0) sh[w] = v;
    __syncthreads();
    int nw = (blockDim.x + 31) >> 5;
    v = (threadIdx.x < nw) ? sh[threadIdx.x] : 0.f;
    if (w==0) v = warpSum(v);
    if (threadIdx.x==0) sh[0] = v;
    __syncthreads();
    v = sh[0];
    __syncthreads();
    return v;
}
__device__ float blockMax(float v){
    __shared__ float shm[32];
    int lane = threadIdx.x & 31, w = threadIdx.x >> 5;
    v = warpMax(v);
    if (lane==0) shm[w] = v;
    __syncthreads();
    int nw = (blockDim.x + 31) >> 5;
    v = (threadIdx.x < nw) ? shm[threadIdx.x] : -1e30f;
    if (w==0) v = warpMax(v);
    if (threadIdx.x==0) shm[0] = v;
    __syncthreads();
    v = shm[0];
    __syncthreads();
    return v;
}

// ---------------- patch embed: depthwise conv only ----------------
__global__ void dwconv_kernel(const float* __restrict__ img,
                              const float* __restrict__ dw_w,
                              const float* __restrict__ dw_b){
    int idx = blockIdx.x*blockDim.x + threadIdx.x;
    if (idx >= BB*3*NT) return;
    int b = idx / (3*NT);
    int rem = idx - b*3*NT;
    int c = rem / NT;
    int n = rem - c*NT;
    int oh = n / 14, ow = n - oh*14;
    const float* im = img + ((size_t)(b*3+c))*222*222;
    const float* wk = dw_w + c*256;
    float acc = 0.f;
    #pragma unroll 4
    for (int kh=0; kh<16; kh++){
        int ih = oh*16 - 1 + kh;
        if ((unsigned)ih >= 222u) continue;
        for (int kw=0; kw<16; kw++){
            int iw = ow*16 - 1 + kw;
            if ((unsigned)iw >= 222u) continue;
            acc += im[ih*222 + iw] * wk[kh*16 + kw];
        }
    }
    g_hdw[idx] = acc + dw_b[c];
}

// ---------------- LN1 fused with addpos + gate stats (xl -> half) ----------
__global__ __launch_bounds__(256) void ln1_kernel(const float* __restrict__ X,
                                                  const float* __restrict__ pos,
                                                  const float* __restrict__ sc,
                                                  const float* __restrict__ bi){
    int row = blockIdx.x;
    int n = row % NT;
    const float* x = X + (size_t)row*DD;
    const float* p = pos + (size_t)n*DD;
    int t = threadIdx.x;
    float v0 = x[t]+p[t], v1 = x[t+256]+p[t+256], v2 = x[t+512]+p[t+512];
    float mean = blockSum(v0+v1+v2) * (1.f/DD);
    float d0 = v0-mean, d1 = v1-mean, d2 = v2-mean;
    float var = blockSum(d0*d0 + d1*d1 + d2*d2) * (1.f/DD);
    float inv = rsqrtf(var + LN_EPS);
    float y0 = d0*inv*sc[t    ] + bi[t    ];
    float y1 = d1*inv*sc[t+256] + bi[t+256];
    float y2 = d2*inv*sc[t+512] + bi[t+512];
    __half* y = g_xl_h + (size_t)row*DD;
    y[t] = __float2half_rn(y0); y[t+256] = __float2half_rn(y1); y[t+512] = __float2half_rn(y2);
    float mx = blockMax(fmaxf(y0, fmaxf(y1, y2)));
    float sm = blockSum(y0+y1+y2);
    if (t==0){ g_maxn[row] = mx; g_aven[row] = sm * (1.f/DD); }
}

// ---------------- LN2 (reads fp32 x2, writes half h2) ----------------
__global__ __launch_bounds__(256) void ln2_kernel(const float* __restrict__ X,
                                                  const float* __restrict__ sc,
                                                  const float* __restrict__ bi){
    int row = blockIdx.x;
    const float* x = X + (size_t)row*DD;
    int t = threadIdx.x;
    float v0 = x[t], v1 = x[t+256], v2 = x[t+512];
    float mean = blockSum(v0+v1+v2) * (1.f/DD);
    float d0 = v0-mean, d1 = v1-mean, d2 = v2-mean;
    float var = blockSum(d0*d0 + d1*d1 + d2*d2) * (1.f/DD);
    float inv = rsqrtf(var + LN_EPS);
    __half* y = g_h2_h + (size_t)row*DD;
    y[t    ] = __float2half_rn(d0*inv*sc[t    ] + bi[t    ]);
    y[t+256] = __float2half_rn(d1*inv*sc[t+256] + bi[t+256]);
    y[t+512] = __float2half_rn(d2*inv*sc[t+512] + bi[t+512]);
}

// ---------------- gate: per-batch (softmax over N) ----------------
__global__ __launch_bounds__(256) void gate1_kernel(){
    int b = blockIdx.x, t = threadIdx.x;
    bool act = t < NT;
    float mn = act ? g_maxn[b*NT+t] : -1e30f;
    float av = act ? g_aven[b*NT+t] : 0.f;
    float maxg = blockMax(mn);
    float aveg = blockSum(av) * (1.f/NT);
    float t1 = maxg * mn;
    float mx = blockMax(act ? t1 : -1e30f);
    float e  = act ? expf(t1 - mx) : 0.f;
    float ss = blockSum(e);
    if (act) g_s1[b*NT+t] = e / ss;
    if (t==0) g_aveg[b] = aveg;
}

// ---------------- gate: cross-batch (softmax over B at each token) --------
__global__ __launch_bounds__(64) void gate2_kernel(){
    int n = blockIdx.x, b = threadIdx.x;
    float t2 = g_aveg[b] * g_aven[b*NT+n];
    float mx = blockMax(t2);
    float e  = expf(t2 - mx);
    float ss = blockSum(e);
    g_gate[b*NT+n] = g_s1[b*NT+n] * (e / ss);
}

// ============================================================================
// attention on mma.sync with FUSED vqv in staging: one block per (b,h).
// ============================================================================
#define ASTR 104
#define PSTR 216
#define QS_OFF 0
#define KS_OFF (208*ASTR)
#define VS_OFF (KS_OFF + 224*ASTR)
#define PS_OFF (VS_OFF + 208*ASTR)
#define PW_OFF (PS_OFF + 208*PSTR)            // float4[96] table (16B aligned)
#define ATTN2_SMEM (PW_OFF*2 + 96*16)         // 224512 bytes

__global__ __launch_bounds__(256,1) void attn_mma_kernel(const float* __restrict__ pw_w,
                                                         const float* __restrict__ pw_b){
    extern __shared__ __half sh[];
    uint32_t sb = smem_u32(sh);
    int b = blockIdx.x, h = blockIdx.y;
    int tid = threadIdx.x, wid = tid >> 5, lane = tid & 31;
    float4* pwS = (float4*)(sh + PW_OFF);

    if (tid < 96){
        int dcol = h*HD + tid;
        pwS[tid] = make_float4(__ldg(pw_w + dcol*3), __ldg(pw_w + dcol*3 + 1),
                               __ldg(pw_w + dcol*3 + 2), __ldg(pw_b + dcol));
    }
    __syncthreads();

    int rbase = b*NT;
    for (int idx = tid; idx < NT*12; idx += 256){
        int n = idx / 12, j8 = (idx - n*12)*8;
        size_t r = (size_t)(rbase + n);
        size_t qb = r*(size_t)D3 + h*HD + j8;
        uint4 tq = *(const uint4*)(g_qkv_h + qb);
        uint4 tk = *(const uint4*)(g_qkv_h + qb + DD);
        uint4 tv = *(const uint4*)(g_qkv_h + qb + 2*DD);
        *(uint4*)(sh + KS_OFF + n*ASTR + j8) = tk;
        float gate = g_gate[r];
        float h0 = g_hdw[(b*3+0)*NT + n];
        float h1 = g_hdw[(b*3+1)*NT + n];
        float h2 = g_hdw[(b*3+2)*NT + n];
        float qf[8], vf[8];
        h8_to_f8(tq, qf);
        h8_to_f8(tv, vf);
        __half2 vh[4], qh[4];
        #pragma unroll
        for (int e2=0;e2<4;e2++){
            float4 w0 = pwS[j8 + 2*e2];
            float4 w1 = pwS[j8 + 2*e2 + 1];
            float xe0 = h0*w0.x + h1*w0.y + h2*w0.z + w0.w;
            float xe1 = h0*w1.x + h1*w1.y + h2*w1.z + w1.w;
            float vv0 = vf[2*e2  ]*gate + xe0;
            float vv1 = vf[2*e2+1]*gate + xe1;
            vh[e2] = __floats2half2_rn(vv0, vv1);
            qh[e2] = __floats2half2_rn(qf[2*e2] + vv0, qf[2*e2+1] + vv1);
        }
        *(uint4*)(sh + VS_OFF + n*ASTR + j8) = *(uint4*)vh;
        *(uint4*)(sh + QS_OFF + n*ASTR + j8) = *(uint4*)qh;
    }
    uint4 z = make_uint4(0,0,0,0);
    for (int idx = tid; idx < (12+28+12)*12; idx += 256){
        int which, row, j8;
        if (idx < 144){ which = 0; row = 196 + idx/12; j8 = (idx%12)*8; }
        else if (idx < 480){ int k = idx-144; which = 1; row = 196 + k/12; j8 = (k%12)*8; }
        else { int k = idx-480; which = 2; row = 196 + k/12; j8 = (k%12)*8; }
        int off = (which==0) ? QS_OFF : (which==1) ? KS_OFF : VS_OFF;
        *(uint4*)(sh + off + row*ASTR + j8) = z;
    }
    __syncthreads();

    int lr = lane >> 2, lc = lane & 3;

    for (int mt = wid; mt < 13; mt += 8){
        uint32_t aq[6][4];
        uint32_t aAddrBase = sb + (uint32_t)((QS_OFF + (mt*16 + (lane & 15))*ASTR + 8*(lane >> 4)) * 2);
        #pragma unroll
        for (int s=0; s<6; s++)
            ldsm_x4(aAddrBase + (uint32_t)(s*16*2), aq[s][0], aq[s][1], aq[s][2], aq[s][3]);

        float sc[26][4];
        #pragma unroll
        for (int nt=0; nt<26; nt++){ sc[nt][0]=0.f; sc[nt][1]=0.f; sc[nt][2]=0.f; sc[nt][3]=0.f; }
        uint32_t kAddrBase = sb + (uint32_t)((KS_OFF + lane*ASTR) * 2);
        #pragma unroll
        for (int gq=0; gq<7; gq++){
            uint32_t kb = kAddrBase + (uint32_t)(gq*32*ASTR*2);
            #pragma unroll
            for (int s=0; s<6; s++){
                uint32_t t0,t1,t2,t3, u0,u1,u2,u3;
                ldsm_x4(kb + (uint32_t)((s*16    )*2), t0,t1,t2,t3);
                ldsm_x4(kb + (uint32_t)((s*16 + 8)*2), u0,u1,u2,u3);
                mma_f16(sc[gq*4+0], aq[s][0],aq[s][1],aq[s][2],aq[s][3], t0,u0);
                mma_f16(sc[gq*4+1], aq[s][0],aq[s][1],aq[s][2],aq[s][3], t1,u1);
                if (gq < 6){
                    mma_f16(sc[gq*4+2], aq[s][0],aq[s][1],aq[s][2],aq[s][3], t2,u2);
                    mma_f16(sc[gq*4+3], aq[s][0],aq[s][1],aq[s][2],aq[s][3], t3,u3);
                }
            }
        }

        float m0 = -1e30f, m1 = -1e30f;
        #pragma unroll
        for (int nt=0; nt<26; nt++){
            int col = nt*8 + 2*lc;
            if (col   >= NT){ sc[nt][0] = -1e30f; sc[nt][2] = -1e30f; }
            if (col+1 >= NT){ sc[nt][1] = -1e30f; sc[nt][3] = -1e30f; }
            m0 = fmaxf(m0, fmaxf(sc[nt][0], sc[nt][1]));
            m1 = fmaxf(m1, fmaxf(sc[nt][2], sc[nt][3]));
        }
        m0 = fmaxf(m0, __shfl_xor_sync(0xffffffffu, m0, 1));
        m0 = fmaxf(m0, __shfl_xor_sync(0xffffffffu, m0, 2));
        m1 = fmaxf(m1, __shfl_xor_sync(0xffffffffu, m1, 1));
        m1 = fmaxf(m1, __shfl_xor_sync(0xffffffffu, m1, 2));

        float s0 = 0.f, s1 = 0.f;
        #pragma unroll
        for (int nt=0; nt<26; nt++){
            sc[nt][0] = __expf(ATTN_SCALE*(sc[nt][0]-m0));
            sc[nt][1] = __expf(ATTN_SCALE*(sc[nt][1]-m0));
            sc[nt][2] = __expf(ATTN_SCALE*(sc[nt][2]-m1));
            sc[nt][3] = __expf(ATTN_SCALE*(sc[nt][3]-m1));
            s0 += sc[nt][0] + sc[nt][1];
            s1 += sc[nt][2] + sc[nt][3];
        }
        s0 += __shfl_xor_sync(0xffffffffu, s0, 1);
        s0 += __shfl_xor_sync(0xffffffffu, s0, 2);
        s1 += __shfl_xor_sync(0xffffffffu, s1, 1);
        s1 += __shfl_xor_sync(0xffffffffu, s1, 2);
        float i0 = 1.f/s0, i1 = 1.f/s1;

        int pr0 = mt*16 + lr, pr1 = pr0 + 8;
        #pragma unroll
        for (int nt=0; nt<26; nt++){
            int col = nt*8 + 2*lc;
            *(__half2*)(sh + PS_OFF + pr0*PSTR + col) = __floats2half2_rn(sc[nt][0]*i0, sc[nt][1]*i0);
            *(__half2*)(sh + PS_OFF + pr1*PSTR + col) = __floats2half2_rn(sc[nt][2]*i1, sc[nt][3]*i1);
        }
        __syncwarp();

        float oc[12][4];
        #pragma unroll
        for (int dt=0; dt<12; dt++){ oc[dt][0]=0.f; oc[dt][1]=0.f; oc[dt][2]=0.f; oc[dt][3]=0.f; }
        uint32_t pAddrBase = sb + (uint32_t)((PS_OFF + (mt*16 + (lane & 15))*PSTR + 8*(lane >> 4)) * 2);
        uint32_t vAddrBase = sb + (uint32_t)((VS_OFF + ((lane & 7) + 8*((lane >> 3) & 1))*ASTR + 8*(lane >> 4)) * 2);
        #pragma unroll
        for (int ks=0; ks<13; ks++){
            uint32_t pa0,pa1,pa2,pa3;
            ldsm_x4(pAddrBase + (uint32_t)(ks*16*2), pa0,pa1,pa2,pa3);
            uint32_t vrow = vAddrBase + (uint32_t)(ks*16*ASTR*2);
            #pragma unroll
            for (int dg=0; dg<6; dg++){
                uint32_t b0,b1,b2,b3;
                ldsm_x4_t(vrow + (uint32_t)(dg*16*2), b0,b1,b2,b3);
                mma_f16(oc[2*dg  ], pa0,pa1,pa2,pa3, b0,b1);
                mma_f16(oc[2*dg+1], pa0,pa1,pa2,pa3, b2,b3);
            }
        }

        int r0 = mt*16 + lr, r1 = r0 + 8;
        __half* o0 = g_att_h + (size_t)(rbase + r0)*DD + h*HD;
        __half* o1 = g_att_h + (size_t)(rbase + r1)*DD + h*HD;
        #pragma unroll
        for (int dt=0; dt<12; dt++){
            int d = dt*8 + 2*lc;
            if (r0 < NT) *(__half2*)(o0 + d) = __floats2half2_rn(oc[dt][0], oc[dt][1]);
            if (r1 < NT) *(__half2*)(o1 + d) = __floats2half2_rn(oc[dt][2], oc[dt][3]);
        }
    }
}

// ---------------- launch ----------------
extern "C" void kernel_launch(void* const* d_in, const int* in_sizes, int n_in,
                              void* d_out, int out_size){
    (void)in_sizes; (void)n_in; (void)out_size;
    const float* x      = (const float*)d_in[0];
    const float* xEem   = (const float*)d_in[1];
    const float* pos    = (const float*)d_in[2];
    const float* dw_w   = (const float*)d_in[3];
    const float* dw_b   = (const float*)d_in[4];
    const float* pw_w   = (const float*)d_in[5];
    const float* pw_b   = (const float*)d_in[6];
    const float* qkv_w  = (const float*)d_in[7];
    const float* proj_w = (const float*)d_in[8];
    const float* proj_b = (const float*)d_in[9];
    const float* ln1_s  = (const float*)d_in[10];
    const float* ln1_b  = (const float*)d_in[11];
    const float* ln2_s  = (const float*)d_in[12];
    const float* ln2_b  = (const float*)d_in[13];
    const float* fc1_w  = (const float*)d_in[14];
    const float* fc1_b  = (const float*)d_in[15];
    const float* fc2_w  = (const float*)d_in[16];
    const float* fc2_b  = (const float*)d_in[17];
    float* out = (float*)d_out;

    float  *p_x2;
    __half *p_xl, *p_qkv, *p_att, *p_h2, *p_fc1;
    __half *p_wqkv, *p_wproj, *p_wfc1, *p_wfc2;
    cudaGetSymbolAddress((void**)&p_xl,  g_xl_h);
    cudaGetSymbolAddress((void**)&p_qkv, g_qkv_h);
    cudaGetSymbolAddress((void**)&p_att, g_att_h);
    cudaGetSymbolAddress((void**)&p_x2,  g_x2);
    cudaGetSymbolAddress((void**)&p_h2,  g_h2_h);
    cudaGetSymbolAddress((void**)&p_fc1, g_fc1_h);
    cudaGetSymbolAddress((void**)&p_wqkv, g_wqkv_h);
    cudaGetSymbolAddress((void**)&p_wproj, g_wproj_h);
    cudaGetSymbolAddress((void**)&p_wfc1, g_wfc1_h);
    cudaGetSymbolAddress((void**)&p_wfc2, g_wfc2_h);

    cudaFuncSetAttribute(hgemm<1>, cudaFuncAttributeMaxDynamicSharedMemorySize, MMA_SMEM);
    cudaFuncSetAttribute(hgemm<2>, cudaFuncAttributeMaxDynamicSharedMemorySize, MMA_SMEM);
    cudaFuncSetAttribute(hgemm<3>, cudaFuncAttributeMaxDynamicSharedMemorySize, MMA_SMEM);
    cudaFuncSetAttribute(hgemm<4>, cudaFuncAttributeMaxDynamicSharedMemorySize, MMA_SMEM);
    cudaFuncSetAttribute(attn_mma_kernel, cudaFuncAttributeMaxDynamicSharedMemorySize,
                         ATTN2_SMEM);

    // all weight fp16 conversions in one launch
    f2h_all_kernel<<<(N4_ALL + 255)/256, 256>>>((const float4*)qkv_w, (const float4*)proj_w,
                                                (const float4*)fc1_w, (const float4*)fc2_w);

    // patch embed depthwise (tiny; feeds attention staging)
    dwconv_kernel<<<(BB*3*NT + 255)/256, 256>>>(xEem, dw_w, dw_b);

    // xl = half(LN1(x + pos)) with gate stats
    ln1_kernel<<<RR, 256>>>(x, pos, ln1_s, ln1_b);

    // gate
    gate1_kernel<<<BB, 256>>>();
    gate2_kernel<<<NT, 64>>>();

    // qkv = xl @ qkv_w^T  -> half
    hgemm<3><<<dim3(D3/128, RR/128), 256, MMA_SMEM>>>(RR, D3, DD, p_xl, p_wqkv,
                                                      nullptr, nullptr, nullptr, p_qkv);

    // attention on tensor cores (vqv fused into staging)
    attn_mma_kernel<<<dim3(BB, HH), 256, ATTN2_SMEM>>>(pw_w, pw_b);

    // x2 = (x + pos) + proj(att)   (fp32)
    hgemm<4><<<dim3(DD/128, RR/128), 256, MMA_SMEM>>>(RR, DD, DD, p_att, p_wproj,
                                                      proj_b, x, pos, p_x2);

    // h2 = half(LN2(x2))
    ln2_kernel<<<RR, 256>>>(p_x2, ln2_s, ln2_b);

    // fc1 + exact GELU -> half
    hgemm<1><<<dim3(D4/128, RR/128), 256, MMA_SMEM>>>(RR, D4, DD, p_h2, p_wfc1,
                                                      fc1_b, nullptr, nullptr, p_fc1);

    // out = x2 + fc2(h)
    hgemm<2><<<dim3(DD/128, RR/128), 256, MMA_SMEM>>>(RR, DD, D4, p_fc1, p_wfc2,
                                                      fc2_b, p_x2, nullptr, out);
}

// round 16
// speedup vs baseline: 1.0104x; 1.0104x over previous
#include <cuda_runtime.h>
#include <cuda_fp16.h>
#include <math.h>
#include <stdint.h>

// ---------------- problem constants ----------------
#define BB   64
#define NT   196
#define DD   768
#define HH   8
#define HD   96
#define RR   (BB*NT)          // 12544 rows
#define D3   (3*DD)           // 2304
#define D4   (4*DD)           // 3072
#define ATTN_SCALE 0.10206207261596577f   // 96^-0.5
#define LN_EPS 1e-5f

// ---------------- scratch (device globals; no allocations allowed) ----------------
static __device__ float  g_hdw [BB*3*NT];
static __device__ __half g_xl_h [RR*DD];
static __device__ __half g_qkv_h[(size_t)RR*D3];
static __device__ __half g_att_h[RR*DD];
static __device__ float  g_x2  [RR*DD];
static __device__ __half g_h2_h[RR*DD];
static __device__ __half g_fc1_h[(size_t)RR*D4];
static __device__ float  g_maxn[RR];
static __device__ float  g_aven[RR];
static __device__ float  g_s1  [RR];
static __device__ float  g_gate[RR];
static __device__ float  g_aveg[BB];
// fp16 weight copies
static __device__ __half g_wqkv_h [(size_t)D3*DD];
static __device__ __half g_wproj_h[(size_t)DD*DD];
static __device__ __half g_wfc1_h [(size_t)D4*DD];
static __device__ __half g_wfc2_h [(size_t)DD*D4];

// ---------------- small helpers ----------------
__device__ __forceinline__ uint32_t smem_u32(const void* p){
    uint32_t a;
    asm("{ .reg .u64 t; cvta.to.shared.u64 t, %1; cvt.u32.u64 %0, t; }" : "=r"(a) : "l"(p));
    return a;
}
__device__ __forceinline__ void cp16(uint32_t dst, const void* src){
    asm volatile("cp.async.cg.shared.global [%0], [%1], 16;" :: "r"(dst), "l"(src));
}
__device__ __forceinline__ void cp_commit(){ asm volatile("cp.async.commit_group;" ::: "memory"); }
template<int N> __device__ __forceinline__ void cp_wait(){
    asm volatile("cp.async.wait_group %0;" :: "n"(N) : "memory");
}
__device__ __forceinline__ void mma_f16(float c[4],
        uint32_t a0, uint32_t a1, uint32_t a2, uint32_t a3,
        uint32_t b0, uint32_t b1){
    asm volatile("mma.sync.aligned.m16n8k16.row.col.f32.f16.f16.f32 "
        "{%0,%1,%2,%3}, {%4,%5,%6,%7}, {%8,%9}, {%0,%1,%2,%3};"
        : "+f"(c[0]), "+f"(c[1]), "+f"(c[2]), "+f"(c[3])
        : "r"(a0), "r"(a1), "r"(a2), "r"(a3), "r"(b0), "r"(b1));
}
__device__ __forceinline__ void ldsm_x4(uint32_t addr,
        uint32_t& r0, uint32_t& r1, uint32_t& r2, uint32_t& r3){
    asm volatile("ldmatrix.sync.aligned.m8n8.x4.shared.b16 {%0,%1,%2,%3}, [%4];"
        : "=r"(r0), "=r"(r1), "=r"(r2), "=r"(r3) : "r"(addr));
}
__device__ __forceinline__ void ldsm_x4_t(uint32_t addr,
        uint32_t& r0, uint32_t& r1, uint32_t& r2, uint32_t& r3){
    asm volatile("ldmatrix.sync.aligned.m8n8.x4.trans.shared.b16 {%0,%1,%2,%3}, [%4];"
        : "=r"(r0), "=r"(r1), "=r"(r2), "=r"(r3) : "r"(addr));
}
__device__ __forceinline__ void h8_to_f8(uint4 t, float* dst){
    float2 f0 = __half22float2(*(__half2*)&t.x);
    float2 f1 = __half22float2(*(__half2*)&t.y);
    float2 f2 = __half22float2(*(__half2*)&t.z);
    float2 f3 = __half22float2(*(__half2*)&t.w);
    dst[0]=f0.x; dst[1]=f0.y; dst[2]=f1.x; dst[3]=f1.y;
    dst[4]=f2.x; dst[5]=f2.y; dst[6]=f3.x; dst[7]=f3.y;
}

// ---------------- all-weights fp16 conversion (single launch) ----------------
#define N4_QKV  (D3*DD/4)
#define N4_PROJ (DD*DD/4)
#define N4_FC1  (D4*DD/4)
#define N4_FC2  (DD*D4/4)
#define N4_ALL  (N4_QKV + N4_PROJ + N4_FC1 + N4_FC2)
__global__ void f2h_all_kernel(const float4* __restrict__ qkv_w,
                               const float4* __restrict__ proj_w,
                               const float4* __restrict__ fc1_w,
                               const float4* __restrict__ fc2_w){
    int i = blockIdx.x*blockDim.x + threadIdx.x;
    if (i >= N4_ALL) return;
    const float4* s; uint2* d; int j = i;
    if (j < N4_QKV){ s = qkv_w; d = (uint2*)g_wqkv_h; }
    else if ((j -= N4_QKV) < N4_PROJ){ s = proj_w; d = (uint2*)g_wproj_h; }
    else if ((j -= N4_PROJ) < N4_FC1){ s = fc1_w; d = (uint2*)g_wfc1_h; }
    else { j -= N4_FC1; s = fc2_w; d = (uint2*)g_wfc2_h; }
    float4 v = s[j];
    uint2 o;
    *(__half2*)&o.x = __floats2half2_rn(v.x, v.y);
    *(__half2*)&o.y = __floats2half2_rn(v.z, v.w);
    d[j] = o;
}

// ============================================================================
// fp16 mma.sync GEMM, cp.async 4-stage (K-tile 32), ldmatrix fragments.
// C[M,N] = A[M,K] @ W[N,K]^T
// EPI: 1 bias+GELU -> half ; 2 bias + res(fp32) -> fp32 ;
//      3 plain -> half     ; 4 bias + (res fp32 + res2[row%NT] fp32) -> fp32
// ============================================================================
#define NSTG 4
#define TSH  40
#define TILEB (128*TSH*2)
#define STGB  (2*TILEB)
#define MMA_SMEM (NSTG*STGB)

template<int EPI>
__global__ __launch_bounds__(256,2) void hgemm(int M, int N, int K,
        const __half* __restrict__ A, const __half* __restrict__ W,
        const float* __restrict__ bias, const float* __restrict__ res,
        const float* __restrict__ res2, void* __restrict__ Cout){
    extern __shared__ char smc[];
    uint32_t sbase = smem_u32(smc);
    int tid = threadIdx.x, wid = tid >> 5, lane = tid & 31;
    int bm = blockIdx.y, bn = blockIdx.x;
    const __half* Ab = A + (size_t)bm*128*K;
    const __half* Wb = W + (size_t)bn*128*K;
    int nk = K >> 5;

    int wm = (wid & 1) * 64;
    int wn = (wid >> 1) * 32;
    int g  = lane >> 2, tg = lane & 3;

    uint32_t aAddr[4];
    #pragma unroll
    for (int mi=0;mi<4;mi++)
        aAddr[mi] = (uint32_t)(((wm + 16*mi + (lane & 15))*TSH + 8*(lane >> 4)) * 2);
    uint32_t bAddr[2];
    #pragma unroll
    for (int ko=0;ko<2;ko++)
        bAddr[ko] = (uint32_t)(TILEB + ((wn + lane)*TSH + 8*ko) * 2);

    int srow = tid & 127;
    const __half* gsrc = ((tid < 128) ? Ab : Wb) + (size_t)srow*K;
    uint32_t sdst = ((tid < 128) ? 0u : (uint32_t)TILEB) + (uint32_t)srow*(TSH*2);

    #pragma unroll
    for (int s=0; s<NSTG-1; s++){
        uint32_t base = sbase + s*STGB + sdst;
        const __half* gp = gsrc + (s << 5);
        #pragma unroll
        for (int kc=0; kc<4; kc++) cp16(base + kc*16, gp + kc*8);
        cp_commit();
    }

    float c[4][4][4];
    #pragma unroll
    for (int mi=0;mi<4;mi++)
        #pragma unroll
        for (int nj=0;nj<4;nj++)
            #pragma unroll
            for (int e=0;e<4;e++) c[mi][nj][e] = 0.f;

    for (int kt=0; kt<nk; kt++){
        cp_wait<NSTG-2>();
        __syncthreads();
        if (kt + NSTG-1 < nk){
            int s = (kt + NSTG-1) % NSTG;
            uint32_t base = sbase + s*STGB + sdst;
            const __half* gp = gsrc + ((kt + NSTG-1) << 5);
            #pragma unroll
            for (int kc=0; kc<4; kc++) cp16(base + kc*16, gp + kc*8);
        }
        cp_commit();

        uint32_t stg = sbase + (uint32_t)((kt % NSTG) * STGB);
        #pragma unroll
        for (int ks=0; ks<2; ks++){
            uint32_t kboff = (uint32_t)(ks*16*2);
            uint32_t a[4][4], b[4][2];
            #pragma unroll
            for (int mi=0;mi<4;mi++)
                ldsm_x4(stg + aAddr[mi] + kboff, a[mi][0], a[mi][1], a[mi][2], a[mi][3]);
            #pragma unroll
            for (int ko=0;ko<2;ko++){
                uint32_t t0,t1,t2,t3;
                ldsm_x4(stg + bAddr[ko] + kboff, t0, t1, t2, t3);
                b[0][ko]=t0; b[1][ko]=t1; b[2][ko]=t2; b[3][ko]=t3;
            }
            #pragma unroll
            for (int mi=0;mi<4;mi++)
                #pragma unroll
                for (int nj=0;nj<4;nj++)
                    mma_f16(c[mi][nj], a[mi][0],a[mi][1],a[mi][2],a[mi][3], b[nj][0],b[nj][1]);
        }
    }

    // hoisted bias (8 loads instead of 64)
    float bv[4][2];
    if (EPI != 3){
        #pragma unroll
        for (int nj=0;nj<4;nj++){
            int col = bn*128 + wn + 8*nj + tg*2;
            bv[nj][0] = __ldg(bias+col);
            bv[nj][1] = __ldg(bias+col+1);
        }
    }

    #pragma unroll
    for (int mi=0;mi<4;mi++){
        int r0 = bm*128 + wm + 16*mi + g;
        #pragma unroll
        for (int rr=0; rr<2; rr++){
            int row = r0 + rr*8;
            #pragma unroll
            for (int nj=0;nj<4;nj++){
                int col = bn*128 + wn + 8*nj + tg*2;
                float v0 = c[mi][nj][rr*2+0];
                float v1 = c[mi][nj][rr*2+1];
                if (EPI != 3){ v0 += bv[nj][0]; v1 += bv[nj][1]; }
                if (EPI == 1){
                    v0 = 0.5f*v0*(1.0f + erff(v0*0.70710678118654752f));
                    v1 = 0.5f*v1*(1.0f + erff(v1*0.70710678118654752f));
                    __half* Crow = (__half*)Cout + (size_t)row*N;
                    *(__half2*)(Crow + col) = __floats2half2_rn(v0, v1);
                } else if (EPI == 2){
                    float2 r2 = *(const float2*)(res + (size_t)row*N + col);
                    v0 += r2.x; v1 += r2.y;
                    float* Crow = (float*)Cout + (size_t)row*N;
                    *(float2*)(Crow + col) = make_float2(v0, v1);
                } else if (EPI == 4){
                    float2 r2 = *(const float2*)(res + (size_t)row*N + col);
                    float2 p2 = *(const float2*)(res2 + (size_t)(row % NT)*N + col);
                    v0 += r2.x + p2.x; v1 += r2.y + p2.y;
                    float* Crow = (float*)Cout + (size_t)row*N;
                    *(float2*)(Crow + col) = make_float2(v0, v1);
                } else {
                    __half* Crow = (__half*)Cout + (size_t)row*N;
                    *(__half2*)(Crow + col) = __floats2half2_rn(v0, v1);
                }
            }
        }
    }
}

// ---------------- reductions ----------------
__device__ __forceinline__ float warpSum(float v){
    #pragma unroll
    for (int o=16;o;o>>=1) v += __shfl_xor_sync(0xffffffffu, v, o);
    return v;
}
__device__ __forceinline__ float warpMax(float v){
    #pragma unroll
    for (int o=16;o;o>>=1) v = fmaxf(v, __shfl_xor_sync(0xffffffffu, v, o));
    return v;
}
__device__ float blockSum(float v){
    __shared__ float sh[32];
    int lane = threadIdx.x & 31, w = threadIdx.x >> 5;
    v = warpSum(v);
    if (lane==0) sh[w] = v;
    __syncthreads();
    int nw = (blockDim.x + 31) >> 5;
    v = (threadIdx.x < nw) ? sh[threadIdx.x] : 0.f;
    if (w==0) v = warpSum(v);
    if (threadIdx.x==0) sh[0] = v;
    __syncthreads();
    v = sh[0];
    __syncthreads();
    return v;
}
__device__ float blockMax(float v){
    __shared__ float shm[32];
    int lane = threadIdx.x & 31, w = threadIdx.x >> 5;
    v = warpMax(v);
    if (lane==0) shm[w] = v;
    __syncthreads();
    int nw = (blockDim.x + 31) >> 5;
    v = (threadIdx.x < nw) ? shm[threadIdx.x] : -1e30f;
    if (w==0) v = warpMax(v);
    if (threadIdx.x==0) shm[0] = v;
    __syncthreads();
    v = shm[0];
    __syncthreads();
    return v;
}

// ---------------- patch embed: depthwise conv only ----------------
__global__ void dwconv_kernel(const float* __restrict__ img,
                              const float* __restrict__ dw_w,
                              const float* __restrict__ dw_b){
    int idx = blockIdx.x*blockDim.x + threadIdx.x;
    if (idx >= BB*3*NT) return;
    int b = idx / (3*NT);
    int rem = idx - b*3*NT;
    int c = rem / NT;
    int n = rem - c*NT;
    int oh = n / 14, ow = n - oh*14;
    const float* im = img + ((size_t)(b*3+c))*222*222;
    const float* wk = dw_w + c*256;
    float acc = 0.f;
    #pragma unroll 4
    for (int kh=0; kh<16; kh++){
        int ih = oh*16 - 1 + kh;
        if ((unsigned)ih >= 222u) continue;
        for (int kw=0; kw<16; kw++){
            int iw = ow*16 - 1 + kw;
            if ((unsigned)iw >= 222u) continue;
            acc += im[ih*222 + iw] * wk[kh*16 + kw];
        }
    }
    g_hdw[idx] = acc + dw_b[c];
}

// ---------------- LN1 fused with addpos + gate stats (xl -> half) ----------
__global__ __launch_bounds__(256) void ln1_kernel(const float* __restrict__ X,
                                                  const float* __restrict__ pos,
                                                  const float* __restrict__ sc,
                                                  const float* __restrict__ bi){
    int row = blockIdx.x;
    int n = row % NT;
    const float* x = X + (size_t)row*DD;
    const float* p = pos + (size_t)n*DD;
    int t = threadIdx.x;
    float v0 = x[t]+p[t], v1 = x[t+256]+p[t+256], v2 = x[t+512]+p[t+512];
    float mean = blockSum(v0+v1+v2) * (1.f/DD);
    float d0 = v0-mean, d1 = v1-mean, d2 = v2-mean;
    float var = blockSum(d0*d0 + d1*d1 + d2*d2) * (1.f/DD);
    float inv = rsqrtf(var + LN_EPS);
    float y0 = d0*inv*sc[t    ] + bi[t    ];
    float y1 = d1*inv*sc[t+256] + bi[t+256];
    float y2 = d2*inv*sc[t+512] + bi[t+512];
    __half* y = g_xl_h + (size_t)row*DD;
    y[t] = __float2half_rn(y0); y[t+256] = __float2half_rn(y1); y[t+512] = __float2half_rn(y2);
    float mx = blockMax(fmaxf(y0, fmaxf(y1, y2)));
    float sm = blockSum(y0+y1+y2);
    if (t==0){ g_maxn[row] = mx; g_aven[row] = sm * (1.f/DD); }
}

// ---------------- LN2 (reads fp32 x2, writes half h2) ----------------
__global__ __launch_bounds__(256) void ln2_kernel(const float* __restrict__ X,
                                                  const float* __restrict__ sc,
                                                  const float* __restrict__ bi){
    int row = blockIdx.x;
    const float* x = X + (size_t)row*DD;
    int t = threadIdx.x;
    float v0 = x[t], v1 = x[t+256], v2 = x[t+512];
    float mean = blockSum(v0+v1+v2) * (1.f/DD);
    float d0 = v0-mean, d1 = v1-mean, d2 = v2-mean;
    float var = blockSum(d0*d0 + d1*d1 + d2*d2) * (1.f/DD);
    float inv = rsqrtf(var + LN_EPS);
    __half* y = g_h2_h + (size_t)row*DD;
    y[t    ] = __float2half_rn(d0*inv*sc[t    ] + bi[t    ]);
    y[t+256] = __float2half_rn(d1*inv*sc[t+256] + bi[t+256]);
    y[t+512] = __float2half_rn(d2*inv*sc[t+512] + bi[t+512]);
}

// ---------------- gate: per-batch (softmax over N) ----------------
__global__ __launch_bounds__(256) void gate1_kernel(){
    int b = blockIdx.x, t = threadIdx.x;
    bool act = t < NT;
    float mn = act ? g_maxn[b*NT+t] : -1e30f;
    float av = act ? g_aven[b*NT+t] : 0.f;
    float maxg = blockMax(mn);
    float aveg = blockSum(av) * (1.f/NT);
    float t1 = maxg * mn;
    float mx = blockMax(act ? t1 : -1e30f);
    float e  = act ? expf(t1 - mx) : 0.f;
    float ss = blockSum(e);
    if (act) g_s1[b*NT+t] = e / ss;
    if (t==0) g_aveg[b] = aveg;
}

// ---------------- gate: cross-batch (softmax over B at each token) --------
__global__ __launch_bounds__(64) void gate2_kernel(){
    int n = blockIdx.x, b = threadIdx.x;
    float t2 = g_aveg[b] * g_aven[b*NT+n];
    float mx = blockMax(t2);
    float e  = expf(t2 - mx);
    float ss = blockSum(e);
    g_gate[b*NT+n] = g_s1[b*NT+n] * (e / ss);
}

// ============================================================================
// attention on mma.sync, vqv fused in staging, P kept in REGISTERS
// (A-fragment of O=P@V == C-fragment of S=Q'K^T; no P smem round-trip).
// one block per (b,h), 256 threads = 8 warps.
// ============================================================================
#define ASTR 104
#define QS_OFF 0
#define KS_OFF (208*ASTR)
#define VS_OFF (KS_OFF + 224*ASTR)
#define PW_OFF (VS_OFF + 208*ASTR)            // float4[96] table (16B aligned)
#define ATTN2_SMEM (PW_OFF*2 + 96*16)         // 134656 bytes

__global__ __launch_bounds__(256,1) void attn_mma_kernel(const float* __restrict__ pw_w,
                                                         const float* __restrict__ pw_b){
    extern __shared__ __half sh[];
    uint32_t sb = smem_u32(sh);
    int b = blockIdx.x, h = blockIdx.y;
    int tid = threadIdx.x, wid = tid >> 5, lane = tid & 31;
    float4* pwS = (float4*)(sh + PW_OFF);

    if (tid < 96){
        int dcol = h*HD + tid;
        pwS[tid] = make_float4(__ldg(pw_w + dcol*3), __ldg(pw_w + dcol*3 + 1),
                               __ldg(pw_w + dcol*3 + 2), __ldg(pw_b + dcol));
    }
    __syncthreads();

    int rbase = b*NT;
    for (int idx = tid; idx < NT*12; idx += 256){
        int n = idx / 12, j8 = (idx - n*12)*8;
        size_t r = (size_t)(rbase + n);
        size_t qb = r*(size_t)D3 + h*HD + j8;
        uint4 tq = *(const uint4*)(g_qkv_h + qb);
        uint4 tk = *(const uint4*)(g_qkv_h + qb + DD);
        uint4 tv = *(const uint4*)(g_qkv_h + qb + 2*DD);
        *(uint4*)(sh + KS_OFF + n*ASTR + j8) = tk;
        float gate = g_gate[r];
        float h0 = g_hdw[(b*3+0)*NT + n];
        float h1 = g_hdw[(b*3+1)*NT + n];
        float h2 = g_hdw[(b*3+2)*NT + n];
        float qf[8], vf[8];
        h8_to_f8(tq, qf);
        h8_to_f8(tv, vf);
        __half2 vh[4], qh[4];
        #pragma unroll
        for (int e2=0;e2<4;e2++){
            float4 w0 = pwS[j8 + 2*e2];
            float4 w1 = pwS[j8 + 2*e2 + 1];
            float xe0 = h0*w0.x + h1*w0.y + h2*w0.z + w0.w;
            float xe1 = h0*w1.x + h1*w1.y + h2*w1.z + w1.w;
            float vv0 = vf[2*e2  ]*gate + xe0;
            float vv1 = vf[2*e2+1]*gate + xe1;
            vh[e2] = __floats2half2_rn(vv0, vv1);
            qh[e2] = __floats2half2_rn(qf[2*e2] + vv0, qf[2*e2+1] + vv1);
        }
        *(uint4*)(sh + VS_OFF + n*ASTR + j8) = *(uint4*)vh;
        *(uint4*)(sh + QS_OFF + n*ASTR + j8) = *(uint4*)qh;
    }
    uint4 z = make_uint4(0,0,0,0);
    for (int idx = tid; idx < (12+28+12)*12; idx += 256){
        int which, row, j8;
        if (idx < 144){ which = 0; row = 196 + idx/12; j8 = (idx%12)*8; }
        else if (idx < 480){ int k = idx-144; which = 1; row = 196 + k/12; j8 = (k%12)*8; }
        else { int k = idx-480; which = 2; row = 196 + k/12; j8 = (k%12)*8; }
        int off = (which==0) ? QS_OFF : (which==1) ? KS_OFF : VS_OFF;
        *(uint4*)(sh + off + row*ASTR + j8) = z;
    }
    __syncthreads();

    int lr = lane >> 2, lc = lane & 3;

    for (int mt = wid; mt < 13; mt += 8){
        uint32_t aq[6][4];
        uint32_t aAddrBase = sb + (uint32_t)((QS_OFF + (mt*16 + (lane & 15))*ASTR + 8*(lane >> 4)) * 2);
        #pragma unroll
        for (int s=0; s<6; s++)
            ldsm_x4(aAddrBase + (uint32_t)(s*16*2), aq[s][0], aq[s][1], aq[s][2], aq[s][3]);

        float sc[26][4];
        #pragma unroll
        for (int nt=0; nt<26; nt++){ sc[nt][0]=0.f; sc[nt][1]=0.f; sc[nt][2]=0.f; sc[nt][3]=0.f; }
        uint32_t kAddrBase = sb + (uint32_t)((KS_OFF + lane*ASTR) * 2);
        #pragma unroll
        for (int gq=0; gq<7; gq++){
            uint32_t kb = kAddrBase + (uint32_t)(gq*32*ASTR*2);
            #pragma unroll
            for (int s=0; s<6; s++){
                uint32_t t0,t1,t2,t3, u0,u1,u2,u3;
                ldsm_x4(kb + (uint32_t)((s*16    )*2), t0,t1,t2,t3);
                ldsm_x4(kb + (uint32_t)((s*16 + 8)*2), u0,u1,u2,u3);
                mma_f16(sc[gq*4+0], aq[s][0],aq[s][1],aq[s][2],aq[s][3], t0,u0);
                mma_f16(sc[gq*4+1], aq[s][0],aq[s][1],aq[s][2],aq[s][3], t1,u1);
                if (gq < 6){
                    mma_f16(sc[gq*4+2], aq[s][0],aq[s][1],aq[s][2],aq[s][3], t2,u2);
                    mma_f16(sc[gq*4+3], aq[s][0],aq[s][1],aq[s][2],aq[s][3], t3,u3);
                }
            }
        }

        float m0 = -1e30f, m1 = -1e30f;
        #pragma unroll
        for (int nt=0; nt<26; nt++){
            int col = nt*8 + 2*lc;
            if (col   >= NT){ sc[nt][0] = -1e30f; sc[nt][2] = -1e30f; }
            if (col+1 >= NT){ sc[nt][1] = -1e30f; sc[nt][3] = -1e30f; }
            m0 = fmaxf(m0, fmaxf(sc[nt][0], sc[nt][1]));
            m1 = fmaxf(m1, fmaxf(sc[nt][2], sc[nt][3]));
        }
        m0 = fmaxf(m0, __shfl_xor_sync(0xffffffffu, m0, 1));
        m0 = fmaxf(m0, __shfl_xor_sync(0xffffffffu, m0, 2));
        m1 = fmaxf(m1, __shfl_xor_sync(0xffffffffu, m1, 1));
        m1 = fmaxf(m1, __shfl_xor_sync(0xffffffffu, m1, 2));

        float s0 = 0.f, s1 = 0.f;
        #pragma unroll
        for (int nt=0; nt<26; nt++){
            sc[nt][0] = __expf(ATTN_SCALE*(sc[nt][0]-m0));
            sc[nt][1] = __expf(ATTN_SCALE*(sc[nt][1]-m0));
            sc[nt][2] = __expf(ATTN_SCALE*(sc[nt][2]-m1));
            sc[nt][3] = __expf(ATTN_SCALE*(sc[nt][3]-m1));
            s0 += sc[nt][0] + sc[nt][1];
            s1 += sc[nt][2] + sc[nt][3];
        }
        s0 += __shfl_xor_sync(0xffffffffu, s0, 1);
        s0 += __shfl_xor_sync(0xffffffffu, s0, 2);
        s1 += __shfl_xor_sync(0xffffffffu, s1, 1);
        s1 += __shfl_xor_sync(0xffffffffu, s1, 2);
        float i0 = 1.f/s0, i1 = 1.f/s1;

        // ---- O = P @ V with P fragments straight from registers ----
        float oc[12][4];
        #pragma unroll
        for (int dt=0; dt<12; dt++){ oc[dt][0]=0.f; oc[dt][1]=0.f; oc[dt][2]=0.f; oc[dt][3]=0.f; }
        uint32_t vAddrBase = sb + (uint32_t)((VS_OFF + ((lane & 7) + 8*((lane >> 3) & 1))*ASTR + 8*(lane >> 4)) * 2);
        #pragma unroll
        for (int ks=0; ks<13; ks++){
            __half2 pa0h = __floats2half2_rn(sc[2*ks  ][0]*i0, sc[2*ks  ][1]*i0);
            __half2 pa1h = __floats2half2_rn(sc[2*ks  ][2]*i1, sc[2*ks  ][3]*i1);
            __half2 pa2h = __floats2half2_rn(sc[2*ks+1][0]*i0, sc[2*ks+1][1]*i0);
            __half2 pa3h = __floats2half2_rn(sc[2*ks+1][2]*i1, sc[2*ks+1][3]*i1);
            uint32_t pa0 = *(uint32_t*)&pa0h;
            uint32_t pa1 = *(uint32_t*)&pa1h;
            uint32_t pa2 = *(uint32_t*)&pa2h;
            uint32_t pa3 = *(uint32_t*)&pa3h;
            uint32_t vrow = vAddrBase + (uint32_t)(ks*16*ASTR*2);
            #pragma unroll
            for (int dg=0; dg<6; dg++){
                uint32_t b0,b1,b2,b3;
                ldsm_x4_t(vrow + (uint32_t)(dg*16*2), b0,b1,b2,b3);
                mma_f16(oc[2*dg  ], pa0,pa1,pa2,pa3, b0,b1);
                mma_f16(oc[2*dg+1], pa0,pa1,pa2,pa3, b2,b3);
            }
        }

        int r0 = mt*16 + lr, r1 = r0 + 8;
        __half* o0 = g_att_h + (size_t)(rbase + r0)*DD + h*HD;
        __half* o1 = g_att_h + (size_t)(rbase + r1)*DD + h*HD;
        #pragma unroll
        for (int dt=0; dt<12; dt++){
            int d = dt*8 + 2*lc;
            if (r0 < NT) *(__half2*)(o0 + d) = __floats2half2_rn(oc[dt][0], oc[dt][1]);
            if (r1 < NT) *(__half2*)(o1 + d) = __floats2half2_rn(oc[dt][2], oc[dt][3]);
        }
    }
}

// ---------------- launch ----------------
extern "C" void kernel_launch(void* const* d_in, const int* in_sizes, int n_in,
                              void* d_out, int out_size){
    (void)in_sizes; (void)n_in; (void)out_size;
    const float* x      = (const float*)d_in[0];
    const float* xEem   = (const float*)d_in[1];
    const float* pos    = (const float*)d_in[2];
    const float* dw_w   = (const float*)d_in[3];
    const float* dw_b   = (const float*)d_in[4];
    const float* pw_w   = (const float*)d_in[5];
    const float* pw_b   = (const float*)d_in[6];
    const float* qkv_w  = (const float*)d_in[7];
    const float* proj_w = (const float*)d_in[8];
    const float* proj_b = (const float*)d_in[9];
    const float* ln1_s  = (const float*)d_in[10];
    const float* ln1_b  = (const float*)d_in[11];
    const float* ln2_s  = (const float*)d_in[12];
    const float* ln2_b  = (const float*)d_in[13];
    const float* fc1_w  = (const float*)d_in[14];
    const float* fc1_b  = (const float*)d_in[15];
    const float* fc2_w  = (const float*)d_in[16];
    const float* fc2_b  = (const float*)d_in[17];
    float* out = (float*)d_out;

    float  *p_x2;
    __half *p_xl, *p_qkv, *p_att, *p_h2, *p_fc1;
    __half *p_wqkv, *p_wproj, *p_wfc1, *p_wfc2;
    cudaGetSymbolAddress((void**)&p_xl,  g_xl_h);
    cudaGetSymbolAddress((void**)&p_qkv, g_qkv_h);
    cudaGetSymbolAddress((void**)&p_att, g_att_h);
    cudaGetSymbolAddress((void**)&p_x2,  g_x2);
    cudaGetSymbolAddress((void**)&p_h2,  g_h2_h);
    cudaGetSymbolAddress((void**)&p_fc1, g_fc1_h);
    cudaGetSymbolAddress((void**)&p_wqkv, g_wqkv_h);
    cudaGetSymbolAddress((void**)&p_wproj, g_wproj_h);
    cudaGetSymbolAddress((void**)&p_wfc1, g_wfc1_h);
    cudaGetSymbolAddress((void**)&p_wfc2, g_wfc2_h);

    cudaFuncSetAttribute(hgemm<1>, cudaFuncAttributeMaxDynamicSharedMemorySize, MMA_SMEM);
    cudaFuncSetAttribute(hgemm<2>, cudaFuncAttributeMaxDynamicSharedMemorySize, MMA_SMEM);
    cudaFuncSetAttribute(hgemm<3>, cudaFuncAttributeMaxDynamicSharedMemorySize, MMA_SMEM);
    cudaFuncSetAttribute(hgemm<4>, cudaFuncAttributeMaxDynamicSharedMemorySize, MMA_SMEM);
    cudaFuncSetAttribute(attn_mma_kernel, cudaFuncAttributeMaxDynamicSharedMemorySize,
                         ATTN2_SMEM);

    // all weight fp16 conversions in one launch
    f2h_all_kernel<<<(N4_ALL + 255)/256, 256>>>((const float4*)qkv_w, (const float4*)proj_w,
                                                (const float4*)fc1_w, (const float4*)fc2_w);

    // patch embed depthwise (tiny; feeds attention staging)
    dwconv_kernel<<<(BB*3*NT + 255)/256, 256>>>(xEem, dw_w, dw_b);

    // xl = half(LN1(x + pos)) with gate stats
    ln1_kernel<<<RR, 256>>>(x, pos, ln1_s, ln1_b);

    // gate
    gate1_kernel<<<BB, 256>>>();
    gate2_kernel<<<NT, 64>>>();

    // qkv = xl @ qkv_w^T  -> half
    hgemm<3><<<dim3(D3/128, RR/128), 256, MMA_SMEM>>>(RR, D3, DD, p_xl, p_wqkv,
                                                      nullptr, nullptr, nullptr, p_qkv);

    // attention on tensor cores (vqv fused into staging, P in registers)
    attn_mma_kernel<<<dim3(BB, HH), 256, ATTN2_SMEM>>>(pw_w, pw_b);

    // x2 = (x + pos) + proj(att)   (fp32)
    hgemm<4><<<dim3(DD/128, RR/128), 256, MMA_SMEM>>>(RR, DD, DD, p_att, p_wproj,
                                                      proj_b, x, pos, p_x2);

    // h2 = half(LN2(x2))
    ln2_kernel<<<RR, 256>>>(p_x2, ln2_s, ln2_b);

    // fc1 + exact GELU -> half
    hgemm<1><<<dim3(D4/128, RR/128), 256, MMA_SMEM>>>(RR, D4, DD, p_h2, p_wfc1,
                                                      fc1_b, nullptr, nullptr, p_fc1);

    // out = x2 + fc2(h)
    hgemm<2><<<dim3(DD/128, RR/128), 256, MMA_SMEM>>>(RR, DD, D4, p_fc1, p_wfc2,
                                                      fc2_b, p_x2, nullptr, out);
}

// round 17
// speedup vs baseline: 1.2822x; 1.2690x over previous
#include <cuda_runtime.h>
#include <cuda_fp16.h>
#include <math.h>
#include <stdint.h>

// ---------------- problem constants ----------------
#define BB   64
#define NT   196
#define DD   768
#define HH   8
#define HD   96
#define RR   (BB*NT)          // 12544 rows
#define D3   (3*DD)           // 2304
#define D4   (4*DD)           // 3072
#define ATTN_SCALE 0.10206207261596577f   // 96^-0.5
#define LN_EPS 1e-5f

// ---------------- scratch (device globals; no allocations allowed) ----------------
static __device__ float  g_hdw [BB*3*NT];
static __device__ __half g_xl_h [RR*DD];
static __device__ __half g_qkv_h[(size_t)RR*D3];
static __device__ __half g_att_h[RR*DD];
static __device__ float  g_x2  [RR*DD];
static __device__ __half g_h2_h[RR*DD];
static __device__ __half g_fc1_h[(size_t)RR*D4];
static __device__ float  g_maxn[RR];
static __device__ float  g_aven[RR];
static __device__ float  g_s1  [RR];
static __device__ float  g_gate[RR];
static __device__ float  g_aveg[BB];
// fp16 weight copies
static __device__ __half g_wqkv_h [(size_t)D3*DD];
static __device__ __half g_wproj_h[(size_t)DD*DD];
static __device__ __half g_wfc1_h [(size_t)D4*DD];
static __device__ __half g_wfc2_h [(size_t)DD*D4];

// ---------------- small helpers ----------------
__device__ __forceinline__ uint32_t smem_u32(const void* p){
    uint32_t a;
    asm("{ .reg .u64 t; cvta.to.shared.u64 t, %1; cvt.u32.u64 %0, t; }" : "=r"(a) : "l"(p));
    return a;
}
__device__ __forceinline__ void cp16(uint32_t dst, const void* src){
    asm volatile("cp.async.cg.shared.global [%0], [%1], 16;" :: "r"(dst), "l"(src));
}
__device__ __forceinline__ void cp_commit(){ asm volatile("cp.async.commit_group;" ::: "memory"); }
template<int N> __device__ __forceinline__ void cp_wait(){
    asm volatile("cp.async.wait_group %0;" :: "n"(N) : "memory");
}
__device__ __forceinline__ void mma_f16(float c[4],
        uint32_t a0, uint32_t a1, uint32_t a2, uint32_t a3,
        uint32_t b0, uint32_t b1){
    asm volatile("mma.sync.aligned.m16n8k16.row.col.f32.f16.f16.f32 "
        "{%0,%1,%2,%3}, {%4,%5,%6,%7}, {%8,%9}, {%0,%1,%2,%3};"
        : "+f"(c[0]), "+f"(c[1]), "+f"(c[2]), "+f"(c[3])
        : "r"(a0), "r"(a1), "r"(a2), "r"(a3), "r"(b0), "r"(b1));
}
__device__ __forceinline__ void ldsm_x4(uint32_t addr,
        uint32_t& r0, uint32_t& r1, uint32_t& r2, uint32_t& r3){
    asm volatile("ldmatrix.sync.aligned.m8n8.x4.shared.b16 {%0,%1,%2,%3}, [%4];"
        : "=r"(r0), "=r"(r1), "=r"(r2), "=r"(r3) : "r"(addr));
}
__device__ __forceinline__ void ldsm_x4_t(uint32_t addr,
        uint32_t& r0, uint32_t& r1, uint32_t& r2, uint32_t& r3){
    asm volatile("ldmatrix.sync.aligned.m8n8.x4.trans.shared.b16 {%0,%1,%2,%3}, [%4];"
        : "=r"(r0), "=r"(r1), "=r"(r2), "=r"(r3) : "r"(addr));
}
__device__ __forceinline__ void h8_to_f8(uint4 t, float* dst){
    float2 f0 = __half22float2(*(__half2*)&t.x);
    float2 f1 = __half22float2(*(__half2*)&t.y);
    float2 f2 = __half22float2(*(__half2*)&t.z);
    float2 f3 = __half22float2(*(__half2*)&t.w);
    dst[0]=f0.x; dst[1]=f0.y; dst[2]=f1.x; dst[3]=f1.y;
    dst[4]=f2.x; dst[5]=f2.y; dst[6]=f3.x; dst[7]=f3.y;
}

// ---------------- all-weights fp16 conversion (single launch) ----------------
#define N4_QKV  (D3*DD/4)
#define N4_PROJ (DD*DD/4)
#define N4_FC1  (D4*DD/4)
#define N4_FC2  (DD*D4/4)
#define N4_ALL  (N4_QKV + N4_PROJ + N4_FC1 + N4_FC2)
__global__ void f2h_all_kernel(const float4* __restrict__ qkv_w,
                               const float4* __restrict__ proj_w,
                               const float4* __restrict__ fc1_w,
                               const float4* __restrict__ fc2_w){
    int i = blockIdx.x*blockDim.x + threadIdx.x;
    if (i >= N4_ALL) return;
    const float4* s; uint2* d; int j = i;
    if (j < N4_QKV){ s = qkv_w; d = (uint2*)g_wqkv_h; }
    else if ((j -= N4_QKV) < N4_PROJ){ s = proj_w; d = (uint2*)g_wproj_h; }
    else if ((j -= N4_PROJ) < N4_FC1){ s = fc1_w; d = (uint2*)g_wfc1_h; }
    else { j -= N4_FC1; s = fc2_w; d = (uint2*)g_wfc2_h; }
    float4 v = s[j];
    uint2 o;
    *(__half2*)&o.x = __floats2half2_rn(v.x, v.y);
    *(__half2*)&o.y = __floats2half2_rn(v.z, v.w);
    d[j] = o;
}

// ============================================================================
// fp16 mma.sync GEMM, cp.async 4-stage (K-tile 32), CTA tile 128x256,
// 8 warps of 64x64. ldmatrix fragments. C[M,N] = A[M,K] @ W[N,K]^T
// EPI: 1 bias+GELU -> half ; 2 bias + res(fp32) -> fp32 ;
//      3 plain -> half     ; 4 bias + (res fp32 + res2[row%NT] fp32) -> fp32
// ============================================================================
#define NSTG 4
#define TSH  40
#define TILEA_B (128*TSH*2)             // 10240 B (A tile per stage)
#define TILEB_B (256*TSH*2)             // 20480 B (B tile per stage)
#define STGB  (TILEA_B + TILEB_B)       // 30720 B
#define MMA_SMEM (NSTG*STGB)            // 122880 B -> 1 CTA/SM

template<int EPI>
__global__ __launch_bounds__(256,1) void hgemm(int M, int N, int K,
        const __half* __restrict__ A, const __half* __restrict__ W,
        const float* __restrict__ bias, const float* __restrict__ res,
        const float* __restrict__ res2, void* __restrict__ Cout){
    extern __shared__ char smc[];
    uint32_t sbase = smem_u32(smc);
    int tid = threadIdx.x, wid = tid >> 5, lane = tid & 31;
    int bm = blockIdx.y, bn = blockIdx.x;
    const __half* Ab = A + (size_t)bm*128*K;
    const __half* Wb = W + (size_t)bn*256*K;
    int nk = K >> 5;

    int wm = (wid & 1) * 64;
    int wn = (wid >> 1) * 64;
    int g  = lane >> 2, tg = lane & 3;

    // A fragment addresses (bytes within stage)
    uint32_t aAddr[4];
    #pragma unroll
    for (int mi=0;mi<4;mi++)
        aAddr[mi] = (uint32_t)(((wm + 16*mi + (lane & 15))*TSH + 8*(lane >> 4)) * 2);
    // B fragment addresses: [row group rg 0/1][k-half ko 0/1]
    uint32_t bAddr[2][2];
    #pragma unroll
    for (int rg=0;rg<2;rg++)
        #pragma unroll
        for (int ko=0;ko<2;ko++)
            bAddr[rg][ko] = (uint32_t)(TILEA_B + ((wn + rg*32 + lane)*TSH + 8*ko) * 2);

    // staging: 1536 chunks/stage = 256 thr x 6 ; t<2 -> A, t>=2 -> B
    int aRow[2], aKc[2], bRow[4], bKc[4];
    #pragma unroll
    for (int t=0;t<2;t++){ int c = tid + 256*t; aRow[t] = c>>2; aKc[t] = c&3; }
    #pragma unroll
    for (int t=0;t<4;t++){ int c = tid + 256*(t+2) - 512; bRow[t] = c>>2; bKc[t] = c&3; }

    #pragma unroll
    for (int s=0; s<NSTG-1; s++){
        uint32_t base = sbase + s*STGB;
        int k0 = s << 5;
        #pragma unroll
        for (int t=0;t<2;t++)
            cp16(base + (uint32_t)(aRow[t]*(TSH*2) + aKc[t]*16),
                 Ab + (size_t)aRow[t]*K + k0 + aKc[t]*8);
        #pragma unroll
        for (int t=0;t<4;t++)
            cp16(base + (uint32_t)(TILEA_B + bRow[t]*(TSH*2) + bKc[t]*16),
                 Wb + (size_t)bRow[t]*K + k0 + bKc[t]*8);
        cp_commit();
    }

    float c[4][8][4];
    #pragma unroll
    for (int mi=0;mi<4;mi++)
        #pragma unroll
        for (int nj=0;nj<8;nj++)
            #pragma unroll
            for (int e=0;e<4;e++) c[mi][nj][e] = 0.f;

    for (int kt=0; kt<nk; kt++){
        cp_wait<NSTG-2>();
        __syncthreads();
        if (kt + NSTG-1 < nk){
            uint32_t base = sbase + (uint32_t)(((kt + NSTG-1) % NSTG) * STGB);
            int k0 = (kt + NSTG-1) << 5;
            #pragma unroll
            for (int t=0;t<2;t++)
                cp16(base + (uint32_t)(aRow[t]*(TSH*2) + aKc[t]*16),
                     Ab + (size_t)aRow[t]*K + k0 + aKc[t]*8);
            #pragma unroll
            for (int t=0;t<4;t++)
                cp16(base + (uint32_t)(TILEA_B + bRow[t]*(TSH*2) + bKc[t]*16),
                     Wb + (size_t)bRow[t]*K + k0 + bKc[t]*8);
        }
        cp_commit();

        uint32_t stg = sbase + (uint32_t)((kt % NSTG) * STGB);
        #pragma unroll
        for (int ks=0; ks<2; ks++){
            uint32_t kboff = (uint32_t)(ks*16*2);
            uint32_t a[4][4], b[8][2];
            #pragma unroll
            for (int mi=0;mi<4;mi++)
                ldsm_x4(stg + aAddr[mi] + kboff, a[mi][0], a[mi][1], a[mi][2], a[mi][3]);
            #pragma unroll
            for (int rg=0;rg<2;rg++)
                #pragma unroll
                for (int ko=0;ko<2;ko++){
                    uint32_t t0,t1,t2,t3;
                    ldsm_x4(stg + bAddr[rg][ko] + kboff, t0, t1, t2, t3);
                    b[rg*4+0][ko]=t0; b[rg*4+1][ko]=t1; b[rg*4+2][ko]=t2; b[rg*4+3][ko]=t3;
                }
            #pragma unroll
            for (int mi=0;mi<4;mi++)
                #pragma unroll
                for (int nj=0;nj<8;nj++)
                    mma_f16(c[mi][nj], a[mi][0],a[mi][1],a[mi][2],a[mi][3], b[nj][0],b[nj][1]);
        }
    }

    // hoisted bias
    float bv[8][2];
    if (EPI != 3){
        #pragma unroll
        for (int nj=0;nj<8;nj++){
            int col = bn*256 + wn + 8*nj + tg*2;
            bv[nj][0] = __ldg(bias+col);
            bv[nj][1] = __ldg(bias+col+1);
        }
    }

    #pragma unroll
    for (int mi=0;mi<4;mi++){
        int r0 = bm*128 + wm + 16*mi + g;
        #pragma unroll
        for (int rr=0; rr<2; rr++){
            int row = r0 + rr*8;
            #pragma unroll
            for (int nj=0;nj<8;nj++){
                int col = bn*256 + wn + 8*nj + tg*2;
                float v0 = c[mi][nj][rr*2+0];
                float v1 = c[mi][nj][rr*2+1];
                if (EPI != 3){ v0 += bv[nj][0]; v1 += bv[nj][1]; }
                if (EPI == 1){
                    v0 = 0.5f*v0*(1.0f + erff(v0*0.70710678118654752f));
                    v1 = 0.5f*v1*(1.0f + erff(v1*0.70710678118654752f));
                    __half* Crow = (__half*)Cout + (size_t)row*N;
                    *(__half2*)(Crow + col) = __floats2half2_rn(v0, v1);
                } else if (EPI == 2){
                    float2 r2 = *(const float2*)(res + (size_t)row*N + col);
                    v0 += r2.x; v1 += r2.y;
                    float* Crow = (float*)Cout + (size_t)row*N;
                    *(float2*)(Crow + col) = make_float2(v0, v1);
                } else if (EPI == 4){
                    float2 r2 = *(const float2*)(res + (size_t)row*N + col);
                    float2 p2 = *(const float2*)(res2 + (size_t)(row % NT)*N + col);
                    v0 += r2.x + p2.x; v1 += r2.y + p2.y;
                    float* Crow = (float*)Cout + (size_t)row*N;
                    *(float2*)(Crow + col) = make_float2(v0, v1);
                } else {
                    __half* Crow = (__half*)Cout + (size_t)row*N;
                    *(__half2*)(Crow + col) = __floats2half2_rn(v0, v1);
                }
            }
        }
    }
}

// ---------------- reductions ----------------
__device__ __forceinline__ float warpSum(float v){
    #pragma unroll
    for (int o=16;o;o>>=1) v += __shfl_xor_sync(0xffffffffu, v, o);
    return v;
}
__device__ __forceinline__ float warpMax(float v){
    #pragma unroll
    for (int o=16;o;o>>=1) v = fmaxf(v, __shfl_xor_sync(0xffffffffu, v, o));
    return v;
}
__device__ float blockSum(float v){
    __shared__ float sh[32];
    int lane = threadIdx.x & 31, w = threadIdx.x >> 5;
    v = warpSum(v);
    if (lane==0) sh[w] = v;
    __syncthreads();
    int nw = (blockDim.x + 31) >> 5;
    v = (threadIdx.x < nw) ? sh[threadIdx.x] : 0.f;
    if (w==0) v = warpSum(v);
    if (threadIdx.x==0) sh[0] = v;
    __syncthreads();
    v = sh[0];
    __syncthreads();
    return v;
}
__device__ float blockMax(float v){
    __shared__ float shm[32];
    int lane = threadIdx.x & 31, w = threadIdx.x >> 5;
    v = warpMax(v);
    if (lane==0) shm[w] = v;
    __syncthreads();
    int nw = (blockDim.x + 31) >> 5;
    v = (threadIdx.x < nw) ? shm[threadIdx.x] : -1e30f;
    if (w==0) v = warpMax(v);
    if (threadIdx.x==0) shm[0] = v;
    __syncthreads();
    v = shm[0];
    __syncthreads();
    return v;
}

// ---------------- patch embed: depthwise conv only ----------------
__global__ void dwconv_kernel(const float* __restrict__ img,
                              const float* __restrict__ dw_w,
                              const float* __restrict__ dw_b){
    int idx = blockIdx.x*blockDim.x + threadIdx.x;
    if (idx >= BB*3*NT) return;
    int b = idx / (3*NT);
    int rem = idx - b*3*NT;
    int c = rem / NT;
    int n = rem - c*NT;
    int oh = n / 14, ow = n - oh*14;
    const float* im = img + ((size_t)(b*3+c))*222*222;
    const float* wk = dw_w + c*256;
    float acc = 0.f;
    #pragma unroll 4
    for (int kh=0; kh<16; kh++){
        int ih = oh*16 - 1 + kh;
        if ((unsigned)ih >= 222u) continue;
        for (int kw=0; kw<16; kw++){
            int iw = ow*16 - 1 + kw;
            if ((unsigned)iw >= 222u) continue;
            acc += im[ih*222 + iw] * wk[kh*16 + kw];
        }
    }
    g_hdw[idx] = acc + dw_b[c];
}

// ---------------- LN1 fused with addpos + gate stats (xl -> half) ----------
__global__ __launch_bounds__(256) void ln1_kernel(const float* __restrict__ X,
                                                  const float* __restrict__ pos,
                                                  const float* __restrict__ sc,
                                                  const float* __restrict__ bi){
    int row = blockIdx.x;
    int n = row % NT;
    const float* x = X + (size_t)row*DD;
    const float* p = pos + (size_t)n*DD;
    int t = threadIdx.x;
    float v0 = x[t]+p[t], v1 = x[t+256]+p[t+256], v2 = x[t+512]+p[t+512];
    float mean = blockSum(v0+v1+v2) * (1.f/DD);
    float d0 = v0-mean, d1 = v1-mean, d2 = v2-mean;
    float var = blockSum(d0*d0 + d1*d1 + d2*d2) * (1.f/DD);
    float inv = rsqrtf(var + LN_EPS);
    float y0 = d0*inv*sc[t    ] + bi[t    ];
    float y1 = d1*inv*sc[t+256] + bi[t+256];
    float y2 = d2*inv*sc[t+512] + bi[t+512];
    __half* y = g_xl_h + (size_t)row*DD;
    y[t] = __float2half_rn(y0); y[t+256] = __float2half_rn(y1); y[t+512] = __float2half_rn(y2);
    float mx = blockMax(fmaxf(y0, fmaxf(y1, y2)));
    float sm = blockSum(y0+y1+y2);
    if (t==0){ g_maxn[row] = mx; g_aven[row] = sm * (1.f/DD); }
}

// ---------------- LN2 (reads fp32 x2, writes half h2) ----------------
__global__ __launch_bounds__(256) void ln2_kernel(const float* __restrict__ X,
                                                  const float* __restrict__ sc,
                                                  const float* __restrict__ bi){
    int row = blockIdx.x;
    const float* x = X + (size_t)row*DD;
    int t = threadIdx.x;
    float v0 = x[t], v1 = x[t+256], v2 = x[t+512];
    float mean = blockSum(v0+v1+v2) * (1.f/DD);
    float d0 = v0-mean, d1 = v1-mean, d2 = v2-mean;
    float var = blockSum(d0*d0 + d1*d1 + d2*d2) * (1.f/DD);
    float inv = rsqrtf(var + LN_EPS);
    __half* y = g_h2_h + (size_t)row*DD;
    y[t    ] = __float2half_rn(d0*inv*sc[t    ] + bi[t    ]);
    y[t+256] = __float2half_rn(d1*inv*sc[t+256] + bi[t+256]);
    y[t+512] = __float2half_rn(d2*inv*sc[t+512] + bi[t+512]);
}

// ---------------- gate: per-batch (softmax over N) ----------------
__global__ __launch_bounds__(256) void gate1_kernel(){
    int b = blockIdx.x, t = threadIdx.x;
    bool act = t < NT;
    float mn = act ? g_maxn[b*NT+t] : -1e30f;
    float av = act ? g_aven[b*NT+t] : 0.f;
    float maxg = blockMax(mn);
    float aveg = blockSum(av) * (1.f/NT);
    float t1 = maxg * mn;
    float mx = blockMax(act ? t1 : -1e30f);
    float e  = act ? expf(t1 - mx) : 0.f;
    float ss = blockSum(e);
    if (act) g_s1[b*NT+t] = e / ss;
    if (t==0) g_aveg[b] = aveg;
}

// ---------------- gate: cross-batch (softmax over B at each token) --------
__global__ __launch_bounds__(64) void gate2_kernel(){
    int n = blockIdx.x, b = threadIdx.x;
    float t2 = g_aveg[b] * g_aven[b*NT+n];
    float mx = blockMax(t2);
    float e  = expf(t2 - mx);
    float ss = blockSum(e);
    g_gate[b*NT+n] = g_s1[b*NT+n] * (e / ss);
}

// ============================================================================
// attention on mma.sync, vqv fused in staging, P kept in REGISTERS.
// one block per (b,h), 256 threads = 8 warps.
// ============================================================================
#define ASTR 104
#define QS_OFF 0
#define KS_OFF (208*ASTR)
#define VS_OFF (KS_OFF + 224*ASTR)
#define PW_OFF (VS_OFF + 208*ASTR)            // float4[96] table (16B aligned)
#define ATTN2_SMEM (PW_OFF*2 + 96*16)         // 134656 bytes

__global__ __launch_bounds__(256,1) void attn_mma_kernel(const float* __restrict__ pw_w,
                                                         const float* __restrict__ pw_b){
    extern __shared__ __half sh[];
    uint32_t sb = smem_u32(sh);
    int b = blockIdx.x, h = blockIdx.y;
    int tid = threadIdx.x, wid = tid >> 5, lane = tid & 31;
    float4* pwS = (float4*)(sh + PW_OFF);

    if (tid < 96){
        int dcol = h*HD + tid;
        pwS[tid] = make_float4(__ldg(pw_w + dcol*3), __ldg(pw_w + dcol*3 + 1),
                               __ldg(pw_w + dcol*3 + 2), __ldg(pw_b + dcol));
    }
    __syncthreads();

    int rbase = b*NT;
    for (int idx = tid; idx < NT*12; idx += 256){
        int n = idx / 12, j8 = (idx - n*12)*8;
        size_t r = (size_t)(rbase + n);
        size_t qb = r*(size_t)D3 + h*HD + j8;
        uint4 tq = *(const uint4*)(g_qkv_h + qb);
        uint4 tk = *(const uint4*)(g_qkv_h + qb + DD);
        uint4 tv = *(const uint4*)(g_qkv_h + qb + 2*DD);
        *(uint4*)(sh + KS_OFF + n*ASTR + j8) = tk;
        float gate = g_gate[r];
        float h0 = g_hdw[(b*3+0)*NT + n];
        float h1 = g_hdw[(b*3+1)*NT + n];
        float h2 = g_hdw[(b*3+2)*NT + n];
        float qf[8], vf[8];
        h8_to_f8(tq, qf);
        h8_to_f8(tv, vf);
        __half2 vh[4], qh[4];
        #pragma unroll
        for (int e2=0;e2<4;e2++){
            float4 w0 = pwS[j8 + 2*e2];
            float4 w1 = pwS[j8 + 2*e2 + 1];
            float xe0 = h0*w0.x + h1*w0.y + h2*w0.z + w0.w;
            float xe1 = h0*w1.x + h1*w1.y + h2*w1.z + w1.w;
            float vv0 = vf[2*e2  ]*gate + xe0;
            float vv1 = vf[2*e2+1]*gate + xe1;
            vh[e2] = __floats2half2_rn(vv0, vv1);
            qh[e2] = __floats2half2_rn(qf[2*e2] + vv0, qf[2*e2+1] + vv1);
        }
        *(uint4*)(sh + VS_OFF + n*ASTR + j8) = *(uint4*)vh;
        *(uint4*)(sh + QS_OFF + n*ASTR + j8) = *(uint4*)qh;
    }
    uint4 z = make_uint4(0,0,0,0);
    for (int idx = tid; idx < (12+28+12)*12; idx += 256){
        int which, row, j8;
        if (idx < 144){ which = 0; row = 196 + idx/12; j8 = (idx%12)*8; }
        else if (idx < 480){ int k = idx-144; which = 1; row = 196 + k/12; j8 = (k%12)*8; }
        else { int k = idx-480; which = 2; row = 196 + k/12; j8 = (k%12)*8; }
        int off = (which==0) ? QS_OFF : (which==1) ? KS_OFF : VS_OFF;
        *(uint4*)(sh + off + row*ASTR + j8) = z;
    }
    __syncthreads();

    int lr = lane >> 2, lc = lane & 3;

    for (int mt = wid; mt < 13; mt += 8){
        uint32_t aq[6][4];
        uint32_t aAddrBase = sb + (uint32_t)((QS_OFF + (mt*16 + (lane & 15))*ASTR + 8*(lane >> 4)) * 2);
        #pragma unroll
        for (int s=0; s<6; s++)
            ldsm_x4(aAddrBase + (uint32_t)(s*16*2), aq[s][0], aq[s][1], aq[s][2], aq[s][3]);

        float sc[26][4];
        #pragma unroll
        for (int nt=0; nt<26; nt++){ sc[nt][0]=0.f; sc[nt][1]=0.f; sc[nt][2]=0.f; sc[nt][3]=0.f; }
        uint32_t kAddrBase = sb + (uint32_t)((KS_OFF + lane*ASTR) * 2);
        #pragma unroll
        for (int gq=0; gq<7; gq++){
            uint32_t kb = kAddrBase + (uint32_t)(gq*32*ASTR*2);
            #pragma unroll
            for (int s=0; s<6; s++){
                uint32_t t0,t1,t2,t3, u0,u1,u2,u3;
                ldsm_x4(kb + (uint32_t)((s*16    )*2), t0,t1,t2,t3);
                ldsm_x4(kb + (uint32_t)((s*16 + 8)*2), u0,u1,u2,u3);
                mma_f16(sc[gq*4+0], aq[s][0],aq[s][1],aq[s][2],aq[s][3], t0,u0);
                mma_f16(sc[gq*4+1], aq[s][0],aq[s][1],aq[s][2],aq[s][3], t1,u1);
                if (gq < 6){
                    mma_f16(sc[gq*4+2], aq[s][0],aq[s][1],aq[s][2],aq[s][3], t2,u2);
                    mma_f16(sc[gq*4+3], aq[s][0],aq[s][1],aq[s][2],aq[s][3], t3,u3);
                }
            }
        }

        float m0 = -1e30f, m1 = -1e30f;
        #pragma unroll
        for (int nt=0; nt<26; nt++){
            int col = nt*8 + 2*lc;
            if (col   >= NT){ sc[nt][0] = -1e30f; sc[nt][2] = -1e30f; }
            if (col+1 >= NT){ sc[nt][1] = -1e30f; sc[nt][3] = -1e30f; }
            m0 = fmaxf(m0, fmaxf(sc[nt][0], sc[nt][1]));
            m1 = fmaxf(m1, fmaxf(sc[nt][2], sc[nt][3]));
        }
        m0 = fmaxf(m0, __shfl_xor_sync(0xffffffffu, m0, 1));
        m0 = fmaxf(m0, __shfl_xor_sync(0xffffffffu, m0, 2));
        m1 = fmaxf(m1, __shfl_xor_sync(0xffffffffu, m1, 1));
        m1 = fmaxf(m1, __shfl_xor_sync(0xffffffffu, m1, 2));

        float s0 = 0.f, s1 = 0.f;
        #pragma unroll
        for (int nt=0; nt<26; nt++){
            sc[nt][0] = __expf(ATTN_SCALE*(sc[nt][0]-m0));
            sc[nt][1] = __expf(ATTN_SCALE*(sc[nt][1]-m0));
            sc[nt][2] = __expf(ATTN_SCALE*(sc[nt][2]-m1));
            sc[nt][3] = __expf(ATTN_SCALE*(sc[nt][3]-m1));
            s0 += sc[nt][0] + sc[nt][1];
            s1 += sc[nt][2] + sc[nt][3];
        }
        s0 += __shfl_xor_sync(0xffffffffu, s0, 1);
        s0 += __shfl_xor_sync(0xffffffffu, s0, 2);
        s1 += __shfl_xor_sync(0xffffffffu, s1, 1);
        s1 += __shfl_xor_sync(0xffffffffu, s1, 2);
        float i0 = 1.f/s0, i1 = 1.f/s1;

        float oc[12][4];
        #pragma unroll
        for (int dt=0; dt<12; dt++){ oc[dt][0]=0.f; oc[dt][1]=0.f; oc[dt][2]=0.f; oc[dt][3]=0.f; }
        uint32_t vAddrBase = sb + (uint32_t)((VS_OFF + ((lane & 7) + 8*((lane >> 3) & 1))*ASTR + 8*(lane >> 4)) * 2);
        #pragma unroll
        for (int ks=0; ks<13; ks++){
            __half2 pa0h = __floats2half2_rn(sc[2*ks  ][0]*i0, sc[2*ks  ][1]*i0);
            __half2 pa1h = __floats2half2_rn(sc[2*ks  ][2]*i1, sc[2*ks  ][3]*i1);
            __half2 pa2h = __floats2half2_rn(sc[2*ks+1][0]*i0, sc[2*ks+1][1]*i0);
            __half2 pa3h = __floats2half2_rn(sc[2*ks+1][2]*i1, sc[2*ks+1][3]*i1);
            uint32_t pa0 = *(uint32_t*)&pa0h;
            uint32_t pa1 = *(uint32_t*)&pa1h;
            uint32_t pa2 = *(uint32_t*)&pa2h;
            uint32_t pa3 = *(uint32_t*)&pa3h;
            uint32_t vrow = vAddrBase + (uint32_t)(ks*16*ASTR*2);
            #pragma unroll
            for (int dg=0; dg<6; dg++){
                uint32_t b0,b1,b2,b3;
                ldsm_x4_t(vrow + (uint32_t)(dg*16*2), b0,b1,b2,b3);
                mma_f16(oc[2*dg  ], pa0,pa1,pa2,pa3, b0,b1);
                mma_f16(oc[2*dg+1], pa0,pa1,pa2,pa3, b2,b3);
            }
        }

        int r0 = mt*16 + lr, r1 = r0 + 8;
        __half* o0 = g_att_h + (size_t)(rbase + r0)*DD + h*HD;
        __half* o1 = g_att_h + (size_t)(rbase + r1)*DD + h*HD;
        #pragma unroll
        for (int dt=0; dt<12; dt++){
            int d = dt*8 + 2*lc;
            if (r0 < NT) *(__half2*)(o0 + d) = __floats2half2_rn(oc[dt][0], oc[dt][1]);
            if (r1 < NT) *(__half2*)(o1 + d) = __floats2half2_rn(oc[dt][2], oc[dt][3]);
        }
    }
}

// ---------------- launch ----------------
extern "C" void kernel_launch(void* const* d_in, const int* in_sizes, int n_in,
                              void* d_out, int out_size){
    (void)in_sizes; (void)n_in; (void)out_size;
    const float* x      = (const float*)d_in[0];
    const float* xEem   = (const float*)d_in[1];
    const float* pos    = (const float*)d_in[2];
    const float* dw_w   = (const float*)d_in[3];
    const float* dw_b   = (const float*)d_in[4];
    const float* pw_w   = (const float*)d_in[5];
    const float* pw_b   = (const float*)d_in[6];
    const float* qkv_w  = (const float*)d_in[7];
    const float* proj_w = (const float*)d_in[8];
    const float* proj_b = (const float*)d_in[9];
    const float* ln1_s  = (const float*)d_in[10];
    const float* ln1_b  = (const float*)d_in[11];
    const float* ln2_s  = (const float*)d_in[12];
    const float* ln2_b  = (const float*)d_in[13];
    const float* fc1_w  = (const float*)d_in[14];
    const float* fc1_b  = (const float*)d_in[15];
    const float* fc2_w  = (const float*)d_in[16];
    const float* fc2_b  = (const float*)d_in[17];
    float* out = (float*)d_out;

    float  *p_x2;
    __half *p_xl, *p_qkv, *p_att, *p_h2, *p_fc1;
    __half *p_wqkv, *p_wproj, *p_wfc1, *p_wfc2;
    cudaGetSymbolAddress((void**)&p_xl,  g_xl_h);
    cudaGetSymbolAddress((void**)&p_qkv, g_qkv_h);
    cudaGetSymbolAddress((void**)&p_att, g_att_h);
    cudaGetSymbolAddress((void**)&p_x2,  g_x2);
    cudaGetSymbolAddress((void**)&p_h2,  g_h2_h);
    cudaGetSymbolAddress((void**)&p_fc1, g_fc1_h);
    cudaGetSymbolAddress((void**)&p_wqkv, g_wqkv_h);
    cudaGetSymbolAddress((void**)&p_wproj, g_wproj_h);
    cudaGetSymbolAddress((void**)&p_wfc1, g_wfc1_h);
    cudaGetSymbolAddress((void**)&p_wfc2, g_wfc2_h);

    cudaFuncSetAttribute(hgemm<1>, cudaFuncAttributeMaxDynamicSharedMemorySize, MMA_SMEM);
    cudaFuncSetAttribute(hgemm<2>, cudaFuncAttributeMaxDynamicSharedMemorySize, MMA_SMEM);
    cudaFuncSetAttribute(hgemm<3>, cudaFuncAttributeMaxDynamicSharedMemorySize, MMA_SMEM);
    cudaFuncSetAttribute(hgemm<4>, cudaFuncAttributeMaxDynamicSharedMemorySize, MMA_SMEM);
    cudaFuncSetAttribute(attn_mma_kernel, cudaFuncAttributeMaxDynamicSharedMemorySize,
                         ATTN2_SMEM);

    // all weight fp16 conversions in one launch
    f2h_all_kernel<<<(N4_ALL + 255)/256, 256>>>((const float4*)qkv_w, (const float4*)proj_w,
                                                (const float4*)fc1_w, (const float4*)fc2_w);

    // patch embed depthwise (tiny; feeds attention staging)
    dwconv_kernel<<<(BB*3*NT + 255)/256, 256>>>(xEem, dw_w, dw_b);

    // xl = half(LN1(x + pos)) with gate stats
    ln1_kernel<<<RR, 256>>>(x, pos, ln1_s, ln1_b);

    // gate
    gate1_kernel<<<BB, 256>>>();
    gate2_kernel<<<NT, 64>>>();

    // qkv = xl @ qkv_w^T  -> half   (N=2304: 9 col blocks)
    hgemm<3><<<dim3(D3/256, RR/128), 256, MMA_SMEM>>>(RR, D3, DD, p_xl, p_wqkv,
                                                      nullptr, nullptr, nullptr, p_qkv);

    // attention on tensor cores (vqv fused, P in registers)
    attn_mma_kernel<<<dim3(BB, HH), 256, ATTN2_SMEM>>>(pw_w, pw_b);

    // x2 = (x + pos) + proj(att)   (fp32; N=768: 3 col blocks)
    hgemm<4><<<dim3(DD/256, RR/128), 256, MMA_SMEM>>>(RR, DD, DD, p_att, p_wproj,
                                                      proj_b, x, pos, p_x2);

    // h2 = half(LN2(x2))
    ln2_kernel<<<RR, 256>>>(p_x2, ln2_s, ln2_b);

    // fc1 + exact GELU -> half   (N=3072: 12 col blocks)
    hgemm<1><<<dim3(D4/256, RR/128), 256, MMA_SMEM>>>(RR, D4, DD, p_h2, p_wfc1,
                                                      fc1_b, nullptr, nullptr, p_fc1);

    // out = x2 + fc2(h)
    hgemm<2><<<dim3(DD/256, RR/128), 256, MMA_SMEM>>>(RR, DD, D4, p_fc1, p_wfc2,
                                                      fc2_b, p_x2, nullptr, out);
}